// round 2
// baseline (speedup 1.0000x reference)
#include <cuda_runtime.h>
#include <math.h>

typedef unsigned long long ull;

#define N_TOTAL 131072
#define ROWS 64
#define NTILES (N_TOTAL / ROWS)   // 2048
#define THREADS 256

#define INV_SQRT_FAN 0.08838834764831845f
#define INV_SQRT3    0.5773502691896258f

// smem layout (float offsets)
#define OFF_W0   0        // [c][o] 128x128
#define OFF_W1   16384    // [c][o] 128x64
#define OFF_B0   24576    // 128
#define OFF_TP0  24704    // tp0T [c][n] 128x64   (reused as Ssm [n][o] 64x128)
#define OFF_A2   32896    // a2T  [c][m] 128x192  (reused as VsmT [o][m] 64x192)
#define SMEM_FLOATS 57472 // 229888 bytes

__device__ __forceinline__ ull pack2(float lo, float hi) {
    ull r; asm("mov.b64 %0, {%1, %2};" : "=l"(r) : "f"(lo), "f"(hi)); return r;
}
__device__ __forceinline__ ull ffma2(ull a, ull b, ull c) {
    ull d; asm("fma.rn.f32x2 %0, %1, %2, %3;" : "=l"(d) : "l"(a), "l"(b), "l"(c)); return d;
}
__device__ __forceinline__ ull fmul2(ull a, ull b) {
    ull d; asm("mul.rn.f32x2 %0, %1, %2;" : "=l"(d) : "l"(a), "l"(b)); return d;
}
__device__ __forceinline__ float sigmoidf_(float v) { return 1.0f / (1.0f + expf(-v)); }
__device__ __forceinline__ float gelu_tanh(float v) {
    // matches jax.nn.gelu(approximate=True)
    float inner = 0.7978845608028654f * (v + 0.044715f * v * v * v);
    return 0.5f * v * (1.0f + tanhf(inner));
}

__global__ void __launch_bounds__(THREADS, 1)
tpl_gate_kernel(const float* __restrict__ x, const float* __restrict__ y,
                const float* __restrict__ W0, const float* __restrict__ b0,
                const float* __restrict__ W1, float* __restrict__ out)
{
    extern __shared__ float smem[];
    float* W0s  = smem + OFF_W0;
    float* W1s  = smem + OFF_W1;
    float* b0s  = smem + OFF_B0;
    float* tp0T = smem + OFF_TP0;   // [c*64 + n]
    float* a2T  = smem + OFF_A2;    // [c*192 + m], m = 3n+i
    float* Ssm  = tp0T;             // [n*128 + o]
    float* VsmT = a2T;              // [o*192 + m]

    const int tid = threadIdx.x;

    // Stage weights + bias once per (persistent) block
    for (int i = tid; i < 16384 / 4; i += THREADS)
        ((float4*)W0s)[i] = ((const float4*)W0)[i];
    for (int i = tid; i < 8192 / 4; i += THREADS)
        ((float4*)W1s)[i] = ((const float4*)W1)[i];
    if (tid < 128) b0s[tid] = b0[tid];

    const int n  = tid >> 2;   // 0..63 (row within tile) for tp-build / epilogue
    const int q  = tid & 3;    // quarter
    const int cg = tid & 15;   // GEMM col group
    const int rg = tid >> 4;   // GEMM row group

    for (int tile = blockIdx.x; tile < NTILES; tile += gridDim.x) {
        const int n0 = tile * ROWS;
        __syncthreads();  // protect tp buffers from previous tile's epilogue reads

        // ---------- build tp0 (transposed) and A2 (transposed, m = 3n+i) ----------
        {
            const float* xg = x + (size_t)(n0 + n) * 256;
            const float* yg = y + (size_t)(n0 + n) * 4;
            const float y0v = yg[0], y11 = yg[1], y12 = yg[2], y13 = yg[3];

            // zone A: c in [q*16, q*16+16): uses x0
            #pragma unroll
            for (int k4 = 0; k4 < 4; k4++) {
                float4 xv = *(const float4*)(xg + q * 16 + k4 * 4);
                float xa[4] = {xv.x, xv.y, xv.z, xv.w};
                #pragma unroll
                for (int e = 0; e < 4; e++) {
                    int c = q * 16 + k4 * 4 + e;
                    float v = xa[e];
                    tp0T[c * 64 + n] = v * y0v;
                    a2T[c * 192 + 3 * n + 0] = v * y11;
                    a2T[c * 192 + 3 * n + 1] = v * y12;
                    a2T[c * 192 + 3 * n + 2] = v * y13;
                }
            }
            // zone B: c in [64+q*16, 64+q*16+16): uses x1 (3 floats per c)
            float buf[48];
            #pragma unroll
            for (int t = 0; t < 12; t++) {
                float4 xv = *(const float4*)(xg + 64 + 48 * q + t * 4);
                buf[t * 4 + 0] = xv.x; buf[t * 4 + 1] = xv.y;
                buf[t * 4 + 2] = xv.z; buf[t * 4 + 3] = xv.w;
            }
            #pragma unroll
            for (int kk = 0; kk < 16; kk++) {
                int c = 64 + q * 16 + kk;
                float t0 = buf[3 * kk], t1 = buf[3 * kk + 1], t2 = buf[3 * kk + 2];
                tp0T[c * 64 + n] = (t0 * y11 + t1 * y12 + t2 * y13) * INV_SQRT3;
                a2T[c * 192 + 3 * n + 0] = t0 * y0v;
                a2T[c * 192 + 3 * n + 1] = t1 * y0v;
                a2T[c * 192 + 3 * n + 2] = t2 * y0v;
            }
        }
        __syncthreads();

        // ---------- GEMM1: S(64x128) = tp0 @ W0 (f32x2, pairs over o) ----------
        {
            const int o0 = cg * 8, r0 = rg * 4;
            ull acc[4][4];
            #pragma unroll
            for (int r = 0; r < 4; r++)
                #pragma unroll
                for (int p = 0; p < 4; p++) acc[r][p] = 0ULL;

            #pragma unroll 4
            for (int c = 0; c < 128; c++) {
                float4 av = *(const float4*)&tp0T[c * 64 + r0];
                ull as[4] = {pack2(av.x, av.x), pack2(av.y, av.y),
                             pack2(av.z, av.z), pack2(av.w, av.w)};
                const ull* bp = (const ull*)&W0s[c * 128 + o0];
                ull bb[4] = {bp[0], bp[1], bp[2], bp[3]};
                #pragma unroll
                for (int r = 0; r < 4; r++)
                    #pragma unroll
                    for (int p = 0; p < 4; p++)
                        acc[r][p] = ffma2(as[r], bb[p], acc[r][p]);
            }
            __syncthreads();  // all tp0T reads done; safe to overwrite as Ssm

            const ull inv2 = pack2(INV_SQRT_FAN, INV_SQRT_FAN);
            #pragma unroll
            for (int r = 0; r < 4; r++)
                #pragma unroll
                for (int p = 0; p < 4; p++) {
                    int o = o0 + 2 * p;
                    ull bbias = *(const ull*)&b0s[o];
                    *(ull*)&Ssm[(r0 + r) * 128 + o] = ffma2(acc[r][p], inv2, bbias);
                }
        }

        // ---------- GEMM2: V(192x64) = A2 @ W1 (f32x2, pairs over m) ----------
        {
            const int o0 = cg * 4, m0 = rg * 12;
            ull acc[6][4];
            #pragma unroll
            for (int pr = 0; pr < 6; pr++)
                #pragma unroll
                for (int j = 0; j < 4; j++) acc[pr][j] = 0ULL;

            #pragma unroll 4
            for (int c = 0; c < 128; c++) {
                const ull* ap = (const ull*)&a2T[c * 192 + m0];
                ull aa[6] = {ap[0], ap[1], ap[2], ap[3], ap[4], ap[5]};
                float4 bv = *(const float4*)&W1s[c * 64 + o0];
                ull bs[4] = {pack2(bv.x, bv.x), pack2(bv.y, bv.y),
                             pack2(bv.z, bv.z), pack2(bv.w, bv.w)};
                #pragma unroll
                for (int pr = 0; pr < 6; pr++)
                    #pragma unroll
                    for (int j = 0; j < 4; j++)
                        acc[pr][j] = ffma2(aa[pr], bs[j], acc[pr][j]);
            }
            __syncthreads();  // all a2T reads done; safe to overwrite as VsmT

            const ull inv2 = pack2(INV_SQRT_FAN, INV_SQRT_FAN);
            #pragma unroll
            for (int pr = 0; pr < 6; pr++)
                #pragma unroll
                for (int j = 0; j < 4; j++)
                    *(ull*)&VsmT[(o0 + j) * 192 + m0 + 2 * pr] = fmul2(acc[pr][j], inv2);
        }
        __syncthreads();

        // ---------- epilogue ----------
        {
            float* outr = out + (size_t)(n0 + n) * 256;

            // Phase A: gates (written back into Ssm) + gelu scalars to gmem
            #pragma unroll
            for (int k = 0; k < 4; k++) {
                int o = q * 16 + k * 4;
                float4 sg = *(float4*)&Ssm[n * 128 + o];
                float4 sc = *(float4*)&Ssm[n * 128 + 64 + o];
                float4 g;
                g.x = sigmoidf_(sg.x); g.y = sigmoidf_(sg.y);
                g.z = sigmoidf_(sg.z); g.w = sigmoidf_(sg.w);
                *(float4*)&Ssm[n * 128 + o] = g;
                float4 e;
                e.x = gelu_tanh(sc.x); e.y = gelu_tanh(sc.y);
                e.z = gelu_tanh(sc.z); e.w = gelu_tanh(sc.w);
                *(float4*)&outr[o] = e;
            }
            __syncthreads();

            // Phase B: vec = gate[n][o] * V[n][o][i], flat j = o*3+i
            #pragma unroll
            for (int k = 0; k < 12; k++) {
                int j0 = q * 48 + k * 4;
                float4 r;
                {
                    int j = j0 + 0; int o = j / 3; int i = j - o * 3;
                    r.x = Ssm[n * 128 + o] * VsmT[o * 192 + 3 * n + i];
                }
                {
                    int j = j0 + 1; int o = j / 3; int i = j - o * 3;
                    r.y = Ssm[n * 128 + o] * VsmT[o * 192 + 3 * n + i];
                }
                {
                    int j = j0 + 2; int o = j / 3; int i = j - o * 3;
                    r.z = Ssm[n * 128 + o] * VsmT[o * 192 + 3 * n + i];
                }
                {
                    int j = j0 + 3; int o = j / 3; int i = j - o * 3;
                    r.w = Ssm[n * 128 + o] * VsmT[o * 192 + 3 * n + i];
                }
                *(float4*)&outr[64 + j0] = r;
            }
        }
    }
}

extern "C" void kernel_launch(void* const* d_in, const int* in_sizes, int n_in,
                              void* d_out, int out_size)
{
    (void)in_sizes; (void)n_in; (void)out_size;
    const float* x  = (const float*)d_in[0];
    const float* y  = (const float*)d_in[1];
    const float* W0 = (const float*)d_in[2];
    const float* b0 = (const float*)d_in[3];
    const float* W1 = (const float*)d_in[4];
    float* out = (float*)d_out;

    const int smem_bytes = SMEM_FLOATS * 4;
    cudaFuncSetAttribute(tpl_gate_kernel,
                         cudaFuncAttributeMaxDynamicSharedMemorySize, smem_bytes);

    int dev = 0;
    cudaGetDevice(&dev);
    int sms = 148;
    cudaDeviceGetAttribute(&sms, cudaDevAttrMultiProcessorCount, dev);
    int grid = sms < NTILES ? sms : NTILES;

    tpl_gate_kernel<<<grid, THREADS, smem_bytes>>>(x, y, W0, b0, W1, out);
}

// round 3
// speedup vs baseline: 1.1257x; 1.1257x over previous
#include <cuda_runtime.h>
#include <math.h>

typedef unsigned long long ull;

#define N_TOTAL 131072
#define ROWS 64
#define NTILES (N_TOTAL / ROWS)   // 2048
#define THREADS 256

#define INV_SQRT_FAN 0.08838834764831845f
#define INV_SQRT3    0.5773502691896258f
#define LOG2E        1.4426950408889634f

// smem layout (float offsets)
#define OFF_W0   0        // W0s [c][o] 128x128
#define OFF_W1   16384    // W1s [c][o] 128x64
#define OFF_B0   24576    // 128
#define OFF_TP0  24704    // tp0T [c*64+n] 128x64  (reused as SsmT [o*65+n] 128x65)
#define OFF_A2   33024    // a2T  [c*192+m] 128x192 (reused as VsmT [o*196+m] 64x196)
#define SMEM_FLOATS 57600 // 230400 bytes

__device__ __forceinline__ ull pack2(float lo, float hi) {
    ull r; asm("mov.b64 %0, {%1, %2};" : "=l"(r) : "f"(lo), "f"(hi)); return r;
}
__device__ __forceinline__ void unpack2(ull v, float& lo, float& hi) {
    asm("mov.b64 {%0, %1}, %2;" : "=f"(lo), "=f"(hi) : "l"(v));
}
__device__ __forceinline__ ull ffma2(ull a, ull b, ull c) {
    ull d; asm("fma.rn.f32x2 %0, %1, %2, %3;" : "=l"(d) : "l"(a), "l"(b), "l"(c)); return d;
}
__device__ __forceinline__ ull fmul2(ull a, ull b) {
    ull d; asm("mul.rn.f32x2 %0, %1, %2;" : "=l"(d) : "l"(a), "l"(b)); return d;
}
__device__ __forceinline__ float ex2f(float v) {
    float r; asm("ex2.approx.f32 %0, %1;" : "=f"(r) : "f"(v)); return r;
}
__device__ __forceinline__ float rcpf(float v) {
    float r; asm("rcp.approx.f32 %0, %1;" : "=f"(r) : "f"(v)); return r;
}
__device__ __forceinline__ float fast_sigmoid(float v) {
    return rcpf(1.0f + ex2f(-LOG2E * v));
}
__device__ __forceinline__ float fast_gelu(float v) {
    // gelu_tanh(v) = 0.5 v (1 + tanh(u)), u = 0.79788456*(v + 0.044715 v^3)
    // tanh(u) = 1 - 2/(1+exp(2u))  =>  gelu = v - v * rcp(1 + exp2(2u*log2e))
    float u = 0.7978845608028654f * v * (1.0f + 0.044715f * v * v);
    float r = rcpf(1.0f + ex2f(2.8853900817779268f * u));
    return v - v * r;
}

__global__ void __launch_bounds__(THREADS, 1)
tpl_gate_kernel(const float* __restrict__ x, const float* __restrict__ y,
                const float* __restrict__ W0, const float* __restrict__ b0,
                const float* __restrict__ W1, float* __restrict__ out)
{
    extern __shared__ float smem[];
    float* W0s  = smem + OFF_W0;
    float* W1s  = smem + OFF_W1;
    float* b0s  = smem + OFF_B0;
    float* tp0T = smem + OFF_TP0;   // [c*64 + n]
    float* SsmT = smem + OFF_TP0;   // [o*65 + n]   (aliases tp0T, after sync)
    float* a2T  = smem + OFF_A2;    // [c*192 + m], m = 3n+i
    float* VsmT = smem + OFF_A2;    // [o*196 + m]  (aliases a2T, after sync)

    const int tid = threadIdx.x;

    // Stage weights + bias once per persistent block
    for (int i = tid; i < 16384 / 4; i += THREADS)
        ((float4*)W0s)[i] = ((const float4*)W0)[i];
    for (int i = tid; i < 8192 / 4; i += THREADS)
        ((float4*)W1s)[i] = ((const float4*)W1)[i];
    if (tid < 128) b0s[tid] = b0[tid];

    // tp-build / epilogue mapping: lanes span 32 distinct n -> conflict-free smem
    const int n  = tid & 63;   // row within tile
    const int q  = tid >> 6;   // quarter
    // GEMM mapping
    const int cg = tid & 15;
    const int rg = tid >> 4;

    for (int tile = blockIdx.x; tile < NTILES; tile += gridDim.x) {
        const int n0 = tile * ROWS;
        __syncthreads();  // protect tp buffers from previous tile's epilogue

        // ---------- build tp0T [c*64+n] and a2T [c*192+3n+i] ----------
        {
            const float* xg = x + (size_t)(n0 + n) * 256;
            const float* yg = y + (size_t)(n0 + n) * 4;
            const float y0v = yg[0], y11 = yg[1], y12 = yg[2], y13 = yg[3];

            // zone A: c in [q*16, q*16+16): uses x0
            #pragma unroll
            for (int k4 = 0; k4 < 4; k4++) {
                float4 xv = *(const float4*)(xg + q * 16 + k4 * 4);
                float xa[4] = {xv.x, xv.y, xv.z, xv.w};
                #pragma unroll
                for (int e = 0; e < 4; e++) {
                    int c = q * 16 + k4 * 4 + e;
                    float v = xa[e];
                    tp0T[c * 64 + n] = v * y0v;
                    a2T[c * 192 + 3 * n + 0] = v * y11;
                    a2T[c * 192 + 3 * n + 1] = v * y12;
                    a2T[c * 192 + 3 * n + 2] = v * y13;
                }
            }
            // zone B: c in [64+q*16, 64+q*16+16): uses x1 (3 floats per c)
            float buf[48];
            #pragma unroll
            for (int t = 0; t < 12; t++) {
                float4 xv = *(const float4*)(xg + 64 + 48 * q + t * 4);
                buf[t * 4 + 0] = xv.x; buf[t * 4 + 1] = xv.y;
                buf[t * 4 + 2] = xv.z; buf[t * 4 + 3] = xv.w;
            }
            #pragma unroll
            for (int kk = 0; kk < 16; kk++) {
                int c = 64 + q * 16 + kk;
                float t0 = buf[3 * kk], t1 = buf[3 * kk + 1], t2 = buf[3 * kk + 2];
                tp0T[c * 64 + n] = (t0 * y11 + t1 * y12 + t2 * y13) * INV_SQRT3;
                a2T[c * 192 + 3 * n + 0] = t0 * y0v;
                a2T[c * 192 + 3 * n + 1] = t1 * y0v;
                a2T[c * 192 + 3 * n + 2] = t2 * y0v;
            }
        }
        __syncthreads();

        // ---------- GEMM1: S(64x128) = tp0 @ W0, f32x2 pairs over o ----------
        {
            const int o0 = cg * 8, r0 = rg * 4;
            ull acc[4][4];
            #pragma unroll
            for (int r = 0; r < 4; r++)
                #pragma unroll
                for (int p = 0; p < 4; p++) acc[r][p] = 0ULL;

            #pragma unroll 4
            for (int c = 0; c < 128; c++) {
                float4 av = *(const float4*)&tp0T[c * 64 + r0];
                ull as[4] = {pack2(av.x, av.x), pack2(av.y, av.y),
                             pack2(av.z, av.z), pack2(av.w, av.w)};
                const ull* bp = (const ull*)&W0s[c * 128 + o0];
                ull bb[4] = {bp[0], bp[1], bp[2], bp[3]};
                #pragma unroll
                for (int r = 0; r < 4; r++)
                    #pragma unroll
                    for (int p = 0; p < 4; p++)
                        acc[r][p] = ffma2(as[r], bb[p], acc[r][p]);
            }
            __syncthreads();  // all tp0T reads done; region becomes SsmT

            #pragma unroll
            for (int r = 0; r < 4; r++)
                #pragma unroll
                for (int p = 0; p < 4; p++) {
                    int o = o0 + 2 * p;
                    float lo, hi;
                    unpack2(acc[r][p], lo, hi);
                    SsmT[o * 65 + r0 + r]       = lo * INV_SQRT_FAN + b0s[o];
                    SsmT[(o + 1) * 65 + r0 + r] = hi * INV_SQRT_FAN + b0s[o + 1];
                }
        }

        // ---------- GEMM2: V(192x64) = A2 @ W1, f32x2 pairs over m ----------
        {
            const int o0 = cg * 4, m0 = rg * 12;
            ull acc[6][4];
            #pragma unroll
            for (int pr = 0; pr < 6; pr++)
                #pragma unroll
                for (int j = 0; j < 4; j++) acc[pr][j] = 0ULL;

            #pragma unroll 4
            for (int c = 0; c < 128; c++) {
                const ull* ap = (const ull*)&a2T[c * 192 + m0];
                ull aa[6] = {ap[0], ap[1], ap[2], ap[3], ap[4], ap[5]};
                float4 bv = *(const float4*)&W1s[c * 64 + o0];
                ull bs[4] = {pack2(bv.x, bv.x), pack2(bv.y, bv.y),
                             pack2(bv.z, bv.z), pack2(bv.w, bv.w)};
                #pragma unroll
                for (int pr = 0; pr < 6; pr++)
                    #pragma unroll
                    for (int j = 0; j < 4; j++)
                        acc[pr][j] = ffma2(aa[pr], bs[j], acc[pr][j]);
            }
            __syncthreads();  // all a2T reads done; region becomes VsmT

            const ull inv2 = pack2(INV_SQRT_FAN, INV_SQRT_FAN);
            #pragma unroll
            for (int pr = 0; pr < 6; pr++)
                #pragma unroll
                for (int j = 0; j < 4; j++)
                    *(ull*)&VsmT[(o0 + j) * 196 + m0 + 2 * pr] = fmul2(acc[pr][j], inv2);
        }
        __syncthreads();

        // ---------- epilogue ----------
        {
            float* outr = out + (size_t)(n0 + n) * 256;

            // Phase A: gates (written back into SsmT) + gelu scalars to gmem
            #pragma unroll
            for (int k4 = 0; k4 < 4; k4++) {
                int ob = q * 16 + k4 * 4;
                float ev[4];
                #pragma unroll
                for (int e = 0; e < 4; e++) {
                    int o = ob + e;
                    float sg = SsmT[o * 65 + n];
                    SsmT[o * 65 + n] = fast_sigmoid(sg);
                    float sc = SsmT[(64 + o) * 65 + n];
                    ev[e] = fast_gelu(sc);
                }
                float4 evv = {ev[0], ev[1], ev[2], ev[3]};
                *(float4*)&outr[ob] = evv;
            }
            __syncthreads();

            // Phase B: vec = gate[n][o] * V[n][o][i], flat j = o*3+i
            // j = q*48 + m, m in [0,48); o = q*16 + m/3; i = m%3 (compile-time)
            #pragma unroll
            for (int k = 0; k < 12; k++) {
                const int m0_ = k * 4;
                float4 r;
                {
                    const int oo = q * 16 + (m0_ + 0) / 3, ii = (m0_ + 0) % 3;
                    r.x = SsmT[oo * 65 + n] * VsmT[oo * 196 + 3 * n + ii];
                }
                {
                    const int oo = q * 16 + (m0_ + 1) / 3, ii = (m0_ + 1) % 3;
                    r.y = SsmT[oo * 65 + n] * VsmT[oo * 196 + 3 * n + ii];
                }
                {
                    const int oo = q * 16 + (m0_ + 2) / 3, ii = (m0_ + 2) % 3;
                    r.z = SsmT[oo * 65 + n] * VsmT[oo * 196 + 3 * n + ii];
                }
                {
                    const int oo = q * 16 + (m0_ + 3) / 3, ii = (m0_ + 3) % 3;
                    r.w = SsmT[oo * 65 + n] * VsmT[oo * 196 + 3 * n + ii];
                }
                *(float4*)&outr[64 + q * 48 + m0_] = r;
            }
        }
    }
}

extern "C" void kernel_launch(void* const* d_in, const int* in_sizes, int n_in,
                              void* d_out, int out_size)
{
    (void)in_sizes; (void)n_in; (void)out_size;
    const float* x  = (const float*)d_in[0];
    const float* y  = (const float*)d_in[1];
    const float* W0 = (const float*)d_in[2];
    const float* b0 = (const float*)d_in[3];
    const float* W1 = (const float*)d_in[4];
    float* out = (float*)d_out;

    const int smem_bytes = SMEM_FLOATS * 4;
    cudaFuncSetAttribute(tpl_gate_kernel,
                         cudaFuncAttributeMaxDynamicSharedMemorySize, smem_bytes);

    int dev = 0;
    cudaGetDevice(&dev);
    int sms = 148;
    cudaDeviceGetAttribute(&sms, cudaDevAttrMultiProcessorCount, dev);
    int grid = sms < NTILES ? sms : NTILES;

    tpl_gate_kernel<<<grid, THREADS, smem_bytes>>>(x, y, W0, b0, W1, out);
}

// round 6
// speedup vs baseline: 2.5327x; 2.2498x over previous
#include <cuda_runtime.h>
#include <cuda_bf16.h>
#include <cstdint>

#define THREADS 256
#define NTILES  2048          // 131072 / 64 rows

#define ISF   0.08838834764831845f
#define IS3   0.5773502691896258f
#define LOG2E 1.4426950408889634f

// ---------------- smem byte offsets ----------------
// slices: s=0..3 (X0,X1,X2,X3), s=4 (E); each: hi 8KB then lo 8KB
#define OFF_SL   0u           // slice(s): OFF_SL + s*16384 (hi), +8192 (lo)
#define OFF_W0A  81920u       // W0a^T [o:128][k:64] hi 16KB, lo +16384
#define OFF_W0B  114688u
#define OFF_W1A  147456u      // W1a^T [o:64][k:64] hi 8KB, lo +8192
#define OFF_W1B  163840u
#define OFF_B0   180224u      // 128 floats
#define OFF_GATE 180736u      // 64 x 66 floats
#define SMEM_BYTES 197632

__device__ __forceinline__ uint32_t sw128(uint32_t o){ return o ^ ((o >> 3) & 0x70); }
__device__ __forceinline__ uint32_t smem_u32(const void* p){
    uint32_t a;
    asm("{ .reg .u64 t; cvta.to.shared.u64 t, %1; cvt.u32.u64 %0, t; }" : "=r"(a) : "l"(p));
    return a;
}
__device__ __forceinline__ void ldsm4(uint32_t* r, uint32_t a){
    asm volatile("ldmatrix.sync.aligned.m8n8.x4.shared.b16 {%0,%1,%2,%3}, [%4];"
        : "=r"(r[0]), "=r"(r[1]), "=r"(r[2]), "=r"(r[3]) : "r"(a));
}
__device__ __forceinline__ void mma16816(float* c, const uint32_t* a, const uint32_t* b){
    asm volatile("mma.sync.aligned.m16n8k16.row.col.f32.bf16.bf16.f32 "
        "{%0,%1,%2,%3}, {%4,%5,%6,%7}, {%8,%9}, {%0,%1,%2,%3};"
        : "+f"(c[0]), "+f"(c[1]), "+f"(c[2]), "+f"(c[3])
        : "r"(a[0]), "r"(a[1]), "r"(a[2]), "r"(a[3]), "r"(b[0]), "r"(b[1]));
}
__device__ __forceinline__ float ex2f(float v){ float r; asm("ex2.approx.f32 %0, %1;" : "=f"(r) : "f"(v)); return r; }
__device__ __forceinline__ float rcpf(float v){ float r; asm("rcp.approx.f32 %0, %1;" : "=f"(r) : "f"(v)); return r; }
__device__ __forceinline__ float fsigmoid(float v){ return rcpf(1.0f + ex2f(-LOG2E * v)); }
__device__ __forceinline__ float fgelu(float v){
    float u = 0.7978845608028654f * v * (1.0f + 0.044715f * v * v);
    return v - v * rcpf(1.0f + ex2f(2.8853900817779268f * u));
}
__device__ __forceinline__ uint32_t packsplit(float a, float b, uint32_t& lo){
    __nv_bfloat16 ha = __float2bfloat16(a), hb = __float2bfloat16(b);
    __nv_bfloat16 la = __float2bfloat16(a - __bfloat162float(ha));
    __nv_bfloat16 lb = __float2bfloat16(b - __bfloat162float(hb));
    lo = (uint32_t)__bfloat16_as_ushort(la) | ((uint32_t)__bfloat16_as_ushort(lb) << 16);
    return (uint32_t)__bfloat16_as_ushort(ha) | ((uint32_t)__bfloat16_as_ushort(hb) << 16);
}
// store 16 consecutive k-values (hi+lo) of one row into a slice
__device__ __forceinline__ void store16(char* sm, uint32_t base, uint32_t o0, const float* f){
    uint32_t hw[8], lw[8];
    #pragma unroll
    for (int j = 0; j < 8; j++) hw[j] = packsplit(f[2*j], f[2*j+1], lw[j]);
    *(uint4*)(sm + base + sw128(o0))             = make_uint4(hw[0], hw[1], hw[2], hw[3]);
    *(uint4*)(sm + base + sw128(o0 + 16))        = make_uint4(hw[4], hw[5], hw[6], hw[7]);
    *(uint4*)(sm + base + 8192u + sw128(o0))     = make_uint4(lw[0], lw[1], lw[2], lw[3]);
    *(uint4*)(sm + base + 8192u + sw128(o0 + 16))= make_uint4(lw[4], lw[5], lw[6], lw[7]);
}

// K=64 GEMM, 3-term bf16 split, accumulate into C[2*NBP][4]
template<int NBP>
__device__ __forceinline__ void gemm3(uint32_t aHi, uint32_t aOff,
                                      uint32_t bHi, uint32_t bLoDelta,
                                      const uint32_t* bOff, float (*C)[4])
{
    #pragma unroll
    for (int ks = 0; ks < 4; ks++){
        uint32_t Ah[4], Al[4];
        uint32_t ao = sw128(aOff + (uint32_t)ks * 32u);
        ldsm4(Ah, aHi + ao);
        ldsm4(Al, aHi + 8192u + ao);
        #pragma unroll
        for (int p = 0; p < NBP; p++){
            uint32_t Bh[4], Bl[4];
            uint32_t bo = sw128(bOff[p] + (uint32_t)ks * 32u);
            ldsm4(Bh, bHi + bo);
            ldsm4(Bl, bHi + bLoDelta + bo);
            mma16816(C[2*p],     Ah, Bh);
            mma16816(C[2*p],     Al, Bh);
            mma16816(C[2*p],     Ah, Bl);
            mma16816(C[2*p + 1], Ah, Bh + 2);
            mma16816(C[2*p + 1], Al, Bh + 2);
            mma16816(C[2*p + 1], Ah, Bl + 2);
        }
    }
}

__global__ void __launch_bounds__(THREADS, 1)
tpl_mma_kernel(const float* __restrict__ x, const float* __restrict__ y,
               const float* __restrict__ W0, const float* __restrict__ b0,
               const float* __restrict__ W1, float* __restrict__ out)
{
    extern __shared__ char sm[];
    const uint32_t smb = smem_u32(sm);
    const int tid = threadIdx.x, lane = tid & 31, w = tid >> 5;
    const int rs = w & 3;            // row strip (16 rows)
    const int h  = w >> 2;           // col half
    const int gid = lane >> 2, tig = lane & 3;

    // ---------------- stage weights (bf16 hi/lo, transposed, SW128) ----------------
    for (int idx = tid; idx < 16384; idx += THREADS){
        int c = idx >> 7, o = idx & 127;
        float v = __ldg(W0 + idx);
        uint32_t base = (c < 64) ? OFF_W0A : OFF_W0B;
        uint32_t off = sw128((uint32_t)o * 128u + (uint32_t)(c & 63) * 2u);
        __nv_bfloat16 hv = __float2bfloat16(v);
        __nv_bfloat16 lv = __float2bfloat16(v - __bfloat162float(hv));
        *(__nv_bfloat16*)(sm + base + off)          = hv;
        *(__nv_bfloat16*)(sm + base + 16384u + off) = lv;
    }
    for (int idx = tid; idx < 8192; idx += THREADS){
        int c = idx >> 6, o = idx & 63;
        float v = __ldg(W1 + idx);
        uint32_t base = (c < 64) ? OFF_W1A : OFF_W1B;
        uint32_t off = sw128((uint32_t)o * 128u + (uint32_t)(c & 63) * 2u);
        __nv_bfloat16 hv = __float2bfloat16(v);
        __nv_bfloat16 lv = __float2bfloat16(v - __bfloat162float(hv));
        *(__nv_bfloat16*)(sm + base + off)         = hv;
        *(__nv_bfloat16*)(sm + base + 8192u + off) = lv;
    }
    if (tid < 128) ((float*)(sm + OFF_B0))[tid] = __ldg(b0 + tid);

    // ---------------- per-lane ldmatrix offsets ----------------
    const uint32_t aOff = (uint32_t)(rs * 16 + (lane & 15)) * 128u
                        + (((uint32_t)lane >> 4) & 1u) * 16u;
    const uint32_t bK    = (((uint32_t)lane >> 3) & 1u) * 16u;
    const uint32_t bLnO  = (uint32_t)(lane & 7) + (((uint32_t)lane >> 4) & 1u) * 8u;
    uint32_t bOffA[4], bOffB[2];
    #pragma unroll
    for (int p = 0; p < 4; p++) bOffA[p] = ((uint32_t)(h * 64 + p * 16) + bLnO) * 128u + bK;
    #pragma unroll
    for (int p = 0; p < 2; p++) bOffB[p] = ((uint32_t)(h * 32 + p * 16) + bLnO) * 128u + bK;

    const int cr = tid >> 2, q = tid & 3;   // convert mapping: row, k-quarter
    float* gateS = (float*)(sm + OFF_GATE);
    const float* b0S = (const float*)(sm + OFF_B0);

    for (int tile = blockIdx.x; tile < NTILES; tile += gridDim.x){
        const int n0 = tile * 64;
        __syncthreads();   // previous tile's smem fully consumed

        // ---------------- convert: build X0..X3, E (bf16 hi/lo) ----------------
        {
            const float* xr = x + (size_t)(n0 + cr) * 256;
            float4 yv = *(const float4*)(y + (size_t)(n0 + cr) * 4);
            uint32_t o0 = (uint32_t)cr * 128u + (uint32_t)q * 32u;
            float f[16];
            #pragma unroll
            for (int j = 0; j < 4; j++){
                float4 v = __ldg((const float4*)xr + q * 4 + j);
                f[4*j] = v.x; f[4*j+1] = v.y; f[4*j+2] = v.z; f[4*j+3] = v.w;
            }
            store16(sm, OFF_SL, o0, f);
            float b[48];
            #pragma unroll
            for (int j = 0; j < 12; j++){
                float4 v = __ldg((const float4*)xr + 16 + q * 12 + j);
                b[4*j] = v.x; b[4*j+1] = v.y; b[4*j+2] = v.z; b[4*j+3] = v.w;
            }
            float f1[16], f2[16], f3[16], fe[16];
            #pragma unroll
            for (int k = 0; k < 16; k++){
                f1[k] = b[3*k]; f2[k] = b[3*k+1]; f3[k] = b[3*k+2];
                fe[k] = IS3 * (yv.y * f1[k] + yv.z * f2[k] + yv.w * f3[k]);
            }
            store16(sm, OFF_SL + 16384u, o0, f1);
            store16(sm, OFF_SL + 32768u, o0, f2);
            store16(sm, OFF_SL + 49152u, o0, f3);
            store16(sm, OFF_SL + 65536u, o0, fe);
        }
        __syncthreads();

        // per-fragment-row y coefficients
        const int gr0 = n0 + rs * 16 + gid, gr1 = gr0 + 8;
        const float4 y0v = *(const float4*)(y + (size_t)gr0 * 4);
        const float4 y1v = *(const float4*)(y + (size_t)gr1 * 4);

        // ---------------- phase A: S = y0*(X0@W0a) + E@W0b ----------------
        {
            float Ct[8][4];
            #pragma unroll
            for (int nb = 0; nb < 8; nb++){ Ct[nb][0]=0.f; Ct[nb][1]=0.f; Ct[nb][2]=0.f; Ct[nb][3]=0.f; }
            gemm3<4>(smb + OFF_SL, aOff, smb + OFF_W0A, 16384u, bOffA, Ct);
            float S[8][4];
            #pragma unroll
            for (int nb = 0; nb < 8; nb++){
                S[nb][0] = y0v.x * Ct[nb][0]; S[nb][1] = y0v.x * Ct[nb][1];
                S[nb][2] = y1v.x * Ct[nb][2]; S[nb][3] = y1v.x * Ct[nb][3];
            }
            gemm3<4>(smb + OFF_SL + 65536u, aOff, smb + OFF_W0B, 16384u, bOffA, S);

            if (h == 0){
                // gate columns 0..63 -> smem
                #pragma unroll
                for (int nb = 0; nb < 8; nb++){
                    int c0 = nb * 8 + 2 * tig;
                    float ba = b0S[c0], bb = b0S[c0 + 1];
                    float2 g0 = { fsigmoid(S[nb][0] * ISF + ba), fsigmoid(S[nb][1] * ISF + bb) };
                    float2 g1 = { fsigmoid(S[nb][2] * ISF + ba), fsigmoid(S[nb][3] * ISF + bb) };
                    *(float2*)&gateS[(rs * 16 + gid) * 66 + c0]     = g0;
                    *(float2*)&gateS[(rs * 16 + gid + 8) * 66 + c0] = g1;
                }
            } else {
                // scalar (gelu) columns 64..127 -> gmem
                #pragma unroll
                for (int nb = 0; nb < 8; nb++){
                    int c0 = 64 + nb * 8 + 2 * tig;
                    float ba = b0S[c0], bb = b0S[c0 + 1];
                    float2 e0 = { fgelu(S[nb][0] * ISF + ba), fgelu(S[nb][1] * ISF + bb) };
                    float2 e1 = { fgelu(S[nb][2] * ISF + ba), fgelu(S[nb][3] * ISF + bb) };
                    *(float2*)(out + (size_t)gr0 * 256 + (c0 - 64)) = e0;
                    *(float2*)(out + (size_t)gr1 * 256 + (c0 - 64)) = e1;
                }
            }
        }
        __syncthreads();   // gates visible

        // ---------------- phase B: V_i = y1i*(X0@W1a) + y0*(Xi@W1b) ----------------
        {
            float P[4][4];
            #pragma unroll
            for (int nb = 0; nb < 4; nb++){ P[nb][0]=0.f; P[nb][1]=0.f; P[nb][2]=0.f; P[nb][3]=0.f; }
            gemm3<2>(smb + OFF_SL, aOff, smb + OFF_W1A, 8192u, bOffB, P);

            float vo[3][4][4];
            #pragma unroll
            for (int i = 0; i < 3; i++){
                float Q[4][4];
                #pragma unroll
                for (int nb = 0; nb < 4; nb++){ Q[nb][0]=0.f; Q[nb][1]=0.f; Q[nb][2]=0.f; Q[nb][3]=0.f; }
                gemm3<2>(smb + OFF_SL + 16384u * (1 + i), aOff, smb + OFF_W1B, 8192u, bOffB, Q);
                const float c1r0 = (&y0v.x)[1 + i] * ISF, c1r1 = (&y1v.x)[1 + i] * ISF;
                const float c0r0 = y0v.x * ISF,           c0r1 = y1v.x * ISF;
                #pragma unroll
                for (int nb = 0; nb < 4; nb++){
                    vo[i][nb][0] = c1r0 * P[nb][0] + c0r0 * Q[nb][0];
                    vo[i][nb][1] = c1r0 * P[nb][1] + c0r0 * Q[nb][1];
                    vo[i][nb][2] = c1r1 * P[nb][2] + c0r1 * Q[nb][2];
                    vo[i][nb][3] = c1r1 * P[nb][3] + c0r1 * Q[nb][3];
                }
            }
            #pragma unroll
            for (int nb = 0; nb < 4; nb++){
                int cB = h * 32 + nb * 8 + 2 * tig;
                float2 ga = *(float2*)&gateS[(rs * 16 + gid) * 66 + cB];
                float2 gb = *(float2*)&gateS[(rs * 16 + gid + 8) * 66 + cB];
                float* o0p = out + (size_t)gr0 * 256 + 64 + 3 * cB;
                float* o1p = out + (size_t)gr1 * 256 + 64 + 3 * cB;
                float2 t;
                t.x = ga.x * vo[0][nb][0]; t.y = ga.x * vo[1][nb][0]; *(float2*)(o0p)     = t;
                t.x = ga.x * vo[2][nb][0]; t.y = ga.y * vo[0][nb][1]; *(float2*)(o0p + 2) = t;
                t.x = ga.y * vo[1][nb][1]; t.y = ga.y * vo[2][nb][1]; *(float2*)(o0p + 4) = t;
                t.x = gb.x * vo[0][nb][2]; t.y = gb.x * vo[1][nb][2]; *(float2*)(o1p)     = t;
                t.x = gb.x * vo[2][nb][2]; t.y = gb.y * vo[0][nb][3]; *(float2*)(o1p + 2) = t;
                t.x = gb.y * vo[1][nb][3]; t.y = gb.y * vo[2][nb][3]; *(float2*)(o1p + 4) = t;
            }
        }
    }
}

extern "C" void kernel_launch(void* const* d_in, const int* in_sizes, int n_in,
                              void* d_out, int out_size)
{
    (void)in_sizes; (void)n_in; (void)out_size;
    const float* x  = (const float*)d_in[0];
    const float* y  = (const float*)d_in[1];
    const float* W0 = (const float*)d_in[2];
    const float* b0 = (const float*)d_in[3];
    const float* W1 = (const float*)d_in[4];
    float* out = (float*)d_out;

    cudaFuncSetAttribute(tpl_mma_kernel,
                         cudaFuncAttributeMaxDynamicSharedMemorySize, SMEM_BYTES);

    int dev = 0;
    cudaGetDevice(&dev);
    int sms = 148;
    cudaDeviceGetAttribute(&sms, cudaDevAttrMultiProcessorCount, dev);
    int grid = sms < NTILES ? sms : NTILES;

    tpl_mma_kernel<<<grid, THREADS, SMEM_BYTES>>>(x, y, W0, b0, W1, out);
}

// round 7
// speedup vs baseline: 2.5943x; 1.0243x over previous
#include <cuda_runtime.h>
#include <cuda_bf16.h>
#include <cstdint>

#define THREADS 256
#define NTILES  2048          // 131072 / 64 rows

#define ISF   0.08838834764831845f
#define IS3   0.5773502691896258f
#define LOG2E 1.4426950408889634f

// ---------------- smem byte offsets ----------------
// slices: s=0..3 (X0,X1,X2,X3), s=4 (E); each: hi 8KB then lo 8KB
#define OFF_SL   0u
#define OFF_W0A  81920u       // W0a^T [o:128][k:64] hi 16KB, lo +16384
#define OFF_W0B  114688u
#define OFF_W1A  147456u      // W1a^T [o:64][k:64] hi 8KB, lo +8192
#define OFF_W1B  163840u
#define OFF_B0   180224u      // 128 floats
#define OFF_GATE 180736u      // 64 rows x 34 floats (gate cols 32..63)
#define SMEM_BYTES 189440

__device__ __forceinline__ uint32_t sw128(uint32_t o){ return o ^ ((o >> 3) & 0x70); }
__device__ __forceinline__ uint32_t smem_u32(const void* p){
    uint32_t a;
    asm("{ .reg .u64 t; cvta.to.shared.u64 t, %1; cvt.u32.u64 %0, t; }" : "=r"(a) : "l"(p));
    return a;
}
__device__ __forceinline__ void ldsm4(uint32_t* r, uint32_t a){
    asm volatile("ldmatrix.sync.aligned.m8n8.x4.shared.b16 {%0,%1,%2,%3}, [%4];"
        : "=r"(r[0]), "=r"(r[1]), "=r"(r[2]), "=r"(r[3]) : "r"(a));
}
__device__ __forceinline__ void mma16816(float* c, const uint32_t* a, const uint32_t* b){
    asm volatile("mma.sync.aligned.m16n8k16.row.col.f32.bf16.bf16.f32 "
        "{%0,%1,%2,%3}, {%4,%5,%6,%7}, {%8,%9}, {%0,%1,%2,%3};"
        : "+f"(c[0]), "+f"(c[1]), "+f"(c[2]), "+f"(c[3])
        : "r"(a[0]), "r"(a[1]), "r"(a[2]), "r"(a[3]), "r"(b[0]), "r"(b[1]));
}
__device__ __forceinline__ float ex2f(float v){ float r; asm("ex2.approx.f32 %0, %1;" : "=f"(r) : "f"(v)); return r; }
__device__ __forceinline__ float rcpf(float v){ float r; asm("rcp.approx.f32 %0, %1;" : "=f"(r) : "f"(v)); return r; }
__device__ __forceinline__ float fsigmoid(float v){ return rcpf(1.0f + ex2f(-LOG2E * v)); }
__device__ __forceinline__ float fgelu(float v){
    float u = 0.7978845608028654f * v * (1.0f + 0.044715f * v * v);
    return v - v * rcpf(1.0f + ex2f(2.8853900817779268f * u));
}
__device__ __forceinline__ uint32_t packsplit(float a, float b, uint32_t& lo){
    __nv_bfloat16 ha = __float2bfloat16(a), hb = __float2bfloat16(b);
    __nv_bfloat16 la = __float2bfloat16(a - __bfloat162float(ha));
    __nv_bfloat16 lb = __float2bfloat16(b - __bfloat162float(hb));
    lo = (uint32_t)__bfloat16_as_ushort(la) | ((uint32_t)__bfloat16_as_ushort(lb) << 16);
    return (uint32_t)__bfloat16_as_ushort(ha) | ((uint32_t)__bfloat16_as_ushort(hb) << 16);
}
__device__ __forceinline__ void store16(char* sm, uint32_t base, uint32_t o0, const float* f){
    uint32_t hw[8], lw[8];
    #pragma unroll
    for (int j = 0; j < 8; j++) hw[j] = packsplit(f[2*j], f[2*j+1], lw[j]);
    *(uint4*)(sm + base + sw128(o0))              = make_uint4(hw[0], hw[1], hw[2], hw[3]);
    *(uint4*)(sm + base + sw128(o0 + 16))         = make_uint4(hw[4], hw[5], hw[6], hw[7]);
    *(uint4*)(sm + base + 8192u + sw128(o0))      = make_uint4(lw[0], lw[1], lw[2], lw[3]);
    *(uint4*)(sm + base + 8192u + sw128(o0 + 16)) = make_uint4(lw[4], lw[5], lw[6], lw[7]);
}

// K=64 GEMM, 3-term bf16 split, accumulate into C[2*NBP][4]
template<int NBP>
__device__ __forceinline__ void gemm3(uint32_t aHi, uint32_t aOff,
                                      uint32_t bHi, uint32_t bLoDelta,
                                      const uint32_t* bOff, float (*C)[4])
{
    #pragma unroll
    for (int ks = 0; ks < 4; ks++){
        uint32_t Ah[4], Al[4];
        uint32_t ao = sw128(aOff + (uint32_t)ks * 32u);
        ldsm4(Ah, aHi + ao);
        ldsm4(Al, aHi + 8192u + ao);
        #pragma unroll
        for (int p = 0; p < NBP; p++){
            uint32_t Bh[4], Bl[4];
            uint32_t bo = sw128(bOff[p] + (uint32_t)ks * 32u);
            ldsm4(Bh, bHi + bo);
            ldsm4(Bl, bHi + bLoDelta + bo);
            mma16816(C[2*p],     Ah, Bh);
            mma16816(C[2*p],     Al, Bh);
            mma16816(C[2*p],     Ah, Bl);
            mma16816(C[2*p + 1], Ah, Bh + 2);
            mma16816(C[2*p + 1], Al, Bh + 2);
            mma16816(C[2*p + 1], Ah, Bl + 2);
        }
    }
}

__global__ void __launch_bounds__(THREADS, 1)
tpl_mma_kernel(const float* __restrict__ x, const float* __restrict__ y,
               const float* __restrict__ W0, const float* __restrict__ b0,
               const float* __restrict__ W1, float* __restrict__ out)
{
    extern __shared__ char sm[];
    const uint32_t smb = smem_u32(sm);
    const int tid = threadIdx.x, lane = tid & 31, w = tid >> 5;
    const int rs = w & 3;            // row strip (16 rows)
    const int h  = w >> 2;           // col half
    const int gid = lane >> 2, tig = lane & 3;

    // ---------------- stage weights (bf16 hi/lo, transposed, SW128) ----------------
    for (int idx = tid; idx < 16384; idx += THREADS){
        int c = idx >> 7, o = idx & 127;
        float v = __ldg(W0 + idx);
        uint32_t base = (c < 64) ? OFF_W0A : OFF_W0B;
        uint32_t off = sw128((uint32_t)o * 128u + (uint32_t)(c & 63) * 2u);
        __nv_bfloat16 hv = __float2bfloat16(v);
        __nv_bfloat16 lv = __float2bfloat16(v - __bfloat162float(hv));
        *(__nv_bfloat16*)(sm + base + off)          = hv;
        *(__nv_bfloat16*)(sm + base + 16384u + off) = lv;
    }
    for (int idx = tid; idx < 8192; idx += THREADS){
        int c = idx >> 6, o = idx & 63;
        float v = __ldg(W1 + idx);
        uint32_t base = (c < 64) ? OFF_W1A : OFF_W1B;
        uint32_t off = sw128((uint32_t)o * 128u + (uint32_t)(c & 63) * 2u);
        __nv_bfloat16 hv = __float2bfloat16(v);
        __nv_bfloat16 lv = __float2bfloat16(v - __bfloat162float(hv));
        *(__nv_bfloat16*)(sm + base + off)         = hv;
        *(__nv_bfloat16*)(sm + base + 8192u + off) = lv;
    }
    if (tid < 128) ((float*)(sm + OFF_B0))[tid] = __ldg(b0 + tid);

    // ---------------- per-lane ldmatrix offsets ----------------
    const uint32_t aOff = (uint32_t)(rs * 16 + (lane & 15)) * 128u
                        + (((uint32_t)lane >> 4) & 1u) * 16u;
    const uint32_t bK    = (((uint32_t)lane >> 3) & 1u) * 16u;
    const uint32_t bLnO  = (uint32_t)(lane & 7) + (((uint32_t)lane >> 4) & 1u) * 8u;
    uint32_t bOffA[4], bOffB[2];
    #pragma unroll
    for (int p = 0; p < 4; p++) bOffA[p] = ((uint32_t)(h * 64 + p * 16) + bLnO) * 128u + bK;
    #pragma unroll
    for (int p = 0; p < 2; p++) bOffB[p] = ((uint32_t)(h * 32 + p * 16) + bLnO) * 128u + bK;

    const int cr = tid >> 2, q = tid & 3;   // convert mapping: row, k-quarter
    float* gate2 = (float*)(sm + OFF_GATE);
    const float* b0S = (const float*)(sm + OFF_B0);

    for (int tile = blockIdx.x; tile < NTILES; tile += gridDim.x){
        const int n0 = tile * 64;
        __syncthreads();   // previous tile's smem (slices + gate2) fully consumed

        // ---------------- convert: build X0..X3, E (bf16 hi/lo) ----------------
        {
            const float* xr = x + (size_t)(n0 + cr) * 256;
            float4 yv = *(const float4*)(y + (size_t)(n0 + cr) * 4);
            uint32_t o0 = (uint32_t)cr * 128u + (uint32_t)q * 32u;
            float f[16];
            #pragma unroll
            for (int j = 0; j < 4; j++){
                float4 v = __ldg((const float4*)xr + q * 4 + j);
                f[4*j] = v.x; f[4*j+1] = v.y; f[4*j+2] = v.z; f[4*j+3] = v.w;
            }
            store16(sm, OFF_SL, o0, f);
            float b[48];
            #pragma unroll
            for (int j = 0; j < 12; j++){
                float4 v = __ldg((const float4*)xr + 16 + q * 12 + j);
                b[4*j] = v.x; b[4*j+1] = v.y; b[4*j+2] = v.z; b[4*j+3] = v.w;
            }
            float f1[16], f2[16], f3[16], fe[16];
            #pragma unroll
            for (int k = 0; k < 16; k++){
                f1[k] = b[3*k]; f2[k] = b[3*k+1]; f3[k] = b[3*k+2];
                fe[k] = IS3 * (yv.y * f1[k] + yv.z * f2[k] + yv.w * f3[k]);
            }
            store16(sm, OFF_SL + 16384u, o0, f1);
            store16(sm, OFF_SL + 32768u, o0, f2);
            store16(sm, OFF_SL + 49152u, o0, f3);
            store16(sm, OFF_SL + 65536u, o0, fe);
        }
        __syncthreads();

        // per-fragment-row y coefficients
        const int gr0 = n0 + rs * 16 + gid, gr1 = gr0 + 8;
        const float4 y0v = *(const float4*)(y + (size_t)gr0 * 4);
        const float4 y1v = *(const float4*)(y + (size_t)gr1 * 4);

        float gown[4][4];   // h==0 warps keep gate cols 0..31 in regs

        // ---------------- phase A: S = y0*(X0@W0a) + E@W0b ----------------
        {
            float S[8][4];
            #pragma unroll
            for (int nb = 0; nb < 8; nb++){ S[nb][0]=0.f; S[nb][1]=0.f; S[nb][2]=0.f; S[nb][3]=0.f; }
            gemm3<4>(smb + OFF_SL, aOff, smb + OFF_W0A, 16384u, bOffA, S);
            #pragma unroll
            for (int nb = 0; nb < 8; nb++){
                S[nb][0] *= y0v.x; S[nb][1] *= y0v.x;
                S[nb][2] *= y1v.x; S[nb][3] *= y1v.x;
            }
            gemm3<4>(smb + OFF_SL + 65536u, aOff, smb + OFF_W0B, 16384u, bOffA, S);

            // -------- epilogue A (no sync needed before phase B GEMMs) --------
            if (h == 0){
                #pragma unroll
                for (int nb = 0; nb < 8; nb++){
                    int c0 = nb * 8 + 2 * tig;
                    float ba = b0S[c0], bb = b0S[c0 + 1];
                    float g0 = fsigmoid(S[nb][0] * ISF + ba);
                    float g1 = fsigmoid(S[nb][1] * ISF + bb);
                    float g2 = fsigmoid(S[nb][2] * ISF + ba);
                    float g3 = fsigmoid(S[nb][3] * ISF + bb);
                    if (nb < 4){
                        gown[nb][0] = g0; gown[nb][1] = g1;
                        gown[nb][2] = g2; gown[nb][3] = g3;
                    } else {
                        float2 t0 = {g0, g1}, t1 = {g2, g3};
                        *(float2*)&gate2[(rs * 16 + gid) * 34 + (nb - 4) * 8 + 2 * tig]     = t0;
                        *(float2*)&gate2[(rs * 16 + gid + 8) * 34 + (nb - 4) * 8 + 2 * tig] = t1;
                    }
                }
            } else {
                #pragma unroll
                for (int nb = 0; nb < 8; nb++){
                    int c0 = 64 + nb * 8 + 2 * tig;
                    float ba = b0S[c0], bb = b0S[c0 + 1];
                    float2 e0 = { fgelu(S[nb][0] * ISF + ba), fgelu(S[nb][1] * ISF + bb) };
                    float2 e1 = { fgelu(S[nb][2] * ISF + ba), fgelu(S[nb][3] * ISF + bb) };
                    *(float2*)(out + (size_t)gr0 * 256 + (c0 - 64)) = e0;
                    *(float2*)(out + (size_t)gr1 * 256 + (c0 - 64)) = e1;
                }
            }
        }

        // ---------------- phase B (fused ks loop, B cached across X1..X3) ----------------
        float P[4][4], Q[3][4][4];
        #pragma unroll
        for (int nb = 0; nb < 4; nb++){ P[nb][0]=0.f; P[nb][1]=0.f; P[nb][2]=0.f; P[nb][3]=0.f; }
        #pragma unroll
        for (int i = 0; i < 3; i++)
            #pragma unroll
            for (int nb = 0; nb < 4; nb++){ Q[i][nb][0]=0.f; Q[i][nb][1]=0.f; Q[i][nb][2]=0.f; Q[i][nb][3]=0.f; }

        #pragma unroll
        for (int ks = 0; ks < 4; ks++){
            const uint32_t ao = sw128(aOff + (uint32_t)ks * 32u);
            uint32_t A0h[4], A0l[4];
            ldsm4(A0h, smb + OFF_SL + ao);
            ldsm4(A0l, smb + OFF_SL + 8192u + ao);
            #pragma unroll
            for (int p = 0; p < 2; p++){
                const uint32_t bo = sw128(bOffB[p] + (uint32_t)ks * 32u);
                uint32_t Bh[4], Bl[4];
                ldsm4(Bh, smb + OFF_W1A + bo);
                ldsm4(Bl, smb + OFF_W1A + 8192u + bo);
                mma16816(P[2*p],     A0h, Bh);
                mma16816(P[2*p],     A0l, Bh);
                mma16816(P[2*p],     A0h, Bl);
                mma16816(P[2*p + 1], A0h, Bh + 2);
                mma16816(P[2*p + 1], A0l, Bh + 2);
                mma16816(P[2*p + 1], A0h, Bl + 2);
            }
            uint32_t Ah[3][4], Al[3][4];
            #pragma unroll
            for (int i = 0; i < 3; i++){
                ldsm4(Ah[i], smb + OFF_SL + 16384u * (1 + i) + ao);
                ldsm4(Al[i], smb + OFF_SL + 16384u * (1 + i) + 8192u + ao);
            }
            #pragma unroll
            for (int p = 0; p < 2; p++){
                const uint32_t bo = sw128(bOffB[p] + (uint32_t)ks * 32u);
                uint32_t Bh[4], Bl[4];
                ldsm4(Bh, smb + OFF_W1B + bo);
                ldsm4(Bl, smb + OFF_W1B + 8192u + bo);
                #pragma unroll
                for (int i = 0; i < 3; i++){
                    mma16816(Q[i][2*p],     Ah[i], Bh);
                    mma16816(Q[i][2*p],     Al[i], Bh);
                    mma16816(Q[i][2*p],     Ah[i], Bl);
                    mma16816(Q[i][2*p + 1], Ah[i], Bh + 2);
                    mma16816(Q[i][2*p + 1], Al[i], Bh + 2);
                    mma16816(Q[i][2*p + 1], Ah[i], Bl + 2);
                }
            }
        }

        __syncthreads();   // gate2 stores (epilogue A) visible to h==1 warps

        // ---------------- epilogue B: vec = gate * (y1i*P + y0*Q_i) ----------------
        {
            const float c0r0 = y0v.x * ISF, c0r1 = y1v.x * ISF;
            #pragma unroll
            for (int nb = 0; nb < 4; nb++){
                float2 ga, gb;
                if (h == 0){
                    ga.x = gown[nb][0]; ga.y = gown[nb][1];
                    gb.x = gown[nb][2]; gb.y = gown[nb][3];
                } else {
                    ga = *(float2*)&gate2[(rs * 16 + gid) * 34 + nb * 8 + 2 * tig];
                    gb = *(float2*)&gate2[(rs * 16 + gid + 8) * 34 + nb * 8 + 2 * tig];
                }
                float vo[3][4];
                #pragma unroll
                for (int i = 0; i < 3; i++){
                    const float c1r0 = (&y0v.x)[1 + i] * ISF, c1r1 = (&y1v.x)[1 + i] * ISF;
                    vo[i][0] = c1r0 * P[nb][0] + c0r0 * Q[i][nb][0];
                    vo[i][1] = c1r0 * P[nb][1] + c0r0 * Q[i][nb][1];
                    vo[i][2] = c1r1 * P[nb][2] + c0r1 * Q[i][nb][2];
                    vo[i][3] = c1r1 * P[nb][3] + c0r1 * Q[i][nb][3];
                }
                const int cB = h * 32 + nb * 8 + 2 * tig;
                float* o0p = out + (size_t)gr0 * 256 + 64 + 3 * cB;
                float* o1p = out + (size_t)gr1 * 256 + 64 + 3 * cB;
                float2 t;
                t.x = ga.x * vo[0][0]; t.y = ga.x * vo[1][0]; *(float2*)(o0p)     = t;
                t.x = ga.x * vo[2][0]; t.y = ga.y * vo[0][1]; *(float2*)(o0p + 2) = t;
                t.x = ga.y * vo[1][1]; t.y = ga.y * vo[2][1]; *(float2*)(o0p + 4) = t;
                t.x = gb.x * vo[0][2]; t.y = gb.x * vo[1][2]; *(float2*)(o1p)     = t;
                t.x = gb.x * vo[2][2]; t.y = gb.y * vo[0][3]; *(float2*)(o1p + 2) = t;
                t.x = gb.y * vo[1][3]; t.y = gb.y * vo[2][3]; *(float2*)(o1p + 4) = t;
            }
        }
    }
}

extern "C" void kernel_launch(void* const* d_in, const int* in_sizes, int n_in,
                              void* d_out, int out_size)
{
    (void)in_sizes; (void)n_in; (void)out_size;
    const float* x  = (const float*)d_in[0];
    const float* y  = (const float*)d_in[1];
    const float* W0 = (const float*)d_in[2];
    const float* b0 = (const float*)d_in[3];
    const float* W1 = (const float*)d_in[4];
    float* out = (float*)d_out;

    cudaFuncSetAttribute(tpl_mma_kernel,
                         cudaFuncAttributeMaxDynamicSharedMemorySize, SMEM_BYTES);

    int dev = 0;
    cudaGetDevice(&dev);
    int sms = 148;
    cudaDeviceGetAttribute(&sms, cudaDevAttrMultiProcessorCount, dev);
    int grid = sms < NTILES ? sms : NTILES;

    tpl_mma_kernel<<<grid, THREADS, SMEM_BYTES>>>(x, y, W0, b0, W1, out);
}

// round 8
// speedup vs baseline: 3.1828x; 1.2268x over previous
#include <cuda_runtime.h>
#include <cuda_bf16.h>
#include <cstdint>

#define THREADS 256
#define NTILES  2048          // 131072 / 64 rows

#define ISF   0.08838834764831845f
#define IS3   0.5773502691896258f
#define LOG2E 1.4426950408889634f

// ---------------- smem byte offsets ----------------
// slices: s=0..3 (X0,X1,X2,X3), s=4 (E); each: hi 8KB then lo 8KB
#define OFF_SL   0u
#define OFF_W0A  81920u       // W0a^T [o:128][k:64] hi 16KB, lo +16384
#define OFF_W0B  114688u
#define OFF_W1A  147456u      // W1a^T [o:64][k:64] hi 8KB, lo +8192
#define OFF_W1B  163840u
#define OFF_B0   180224u      // 128 floats
#define OFF_GATE 180736u      // 64 rows x 34 floats (gate cols 32..63)
#define SMEM_BYTES 189440

__device__ __forceinline__ uint32_t sw128(uint32_t o){ return o ^ ((o >> 3) & 0x70); }
__device__ __forceinline__ uint32_t smem_u32(const void* p){
    uint32_t a;
    asm("{ .reg .u64 t; cvta.to.shared.u64 t, %1; cvt.u32.u64 %0, t; }" : "=r"(a) : "l"(p));
    return a;
}
__device__ __forceinline__ void ldsm4(uint32_t* r, uint32_t a){
    asm volatile("ldmatrix.sync.aligned.m8n8.x4.shared.b16 {%0,%1,%2,%3}, [%4];"
        : "=r"(r[0]), "=r"(r[1]), "=r"(r[2]), "=r"(r[3]) : "r"(a));
}
__device__ __forceinline__ void mma16816(float* c, const uint32_t* a, const uint32_t* b){
    asm volatile("mma.sync.aligned.m16n8k16.row.col.f32.bf16.bf16.f32 "
        "{%0,%1,%2,%3}, {%4,%5,%6,%7}, {%8,%9}, {%0,%1,%2,%3};"
        : "+f"(c[0]), "+f"(c[1]), "+f"(c[2]), "+f"(c[3])
        : "r"(a[0]), "r"(a[1]), "r"(a[2]), "r"(a[3]), "r"(b[0]), "r"(b[1]));
}
// per-strip barrier: 2 warps (64 threads), ids 1..4
#define BARS(id) asm volatile("bar.sync %0, %1;" :: "r"(id), "r"(64) : "memory")

__device__ __forceinline__ float ex2f(float v){ float r; asm("ex2.approx.f32 %0, %1;" : "=f"(r) : "f"(v)); return r; }
__device__ __forceinline__ float rcpf(float v){ float r; asm("rcp.approx.f32 %0, %1;" : "=f"(r) : "f"(v)); return r; }
__device__ __forceinline__ float fsigmoid(float v){ return rcpf(1.0f + ex2f(-LOG2E * v)); }
__device__ __forceinline__ float fgelu(float v){
    float u = 0.7978845608028654f * v * (1.0f + 0.044715f * v * v);
    return v - v * rcpf(1.0f + ex2f(2.8853900817779268f * u));
}
__device__ __forceinline__ uint32_t packsplit(float a, float b, uint32_t& lo){
    __nv_bfloat16 ha = __float2bfloat16(a), hb = __float2bfloat16(b);
    __nv_bfloat16 la = __float2bfloat16(a - __bfloat162float(ha));
    __nv_bfloat16 lb = __float2bfloat16(b - __bfloat162float(hb));
    lo = (uint32_t)__bfloat16_as_ushort(la) | ((uint32_t)__bfloat16_as_ushort(lb) << 16);
    return (uint32_t)__bfloat16_as_ushort(ha) | ((uint32_t)__bfloat16_as_ushort(hb) << 16);
}
__device__ __forceinline__ void store16(char* sm, uint32_t base, uint32_t o0, const float* f){
    uint32_t hw[8], lw[8];
    #pragma unroll
    for (int j = 0; j < 8; j++) hw[j] = packsplit(f[2*j], f[2*j+1], lw[j]);
    *(uint4*)(sm + base + sw128(o0))              = make_uint4(hw[0], hw[1], hw[2], hw[3]);
    *(uint4*)(sm + base + sw128(o0 + 16))         = make_uint4(hw[4], hw[5], hw[6], hw[7]);
    *(uint4*)(sm + base + 8192u + sw128(o0))      = make_uint4(lw[0], lw[1], lw[2], lw[3]);
    *(uint4*)(sm + base + 8192u + sw128(o0 + 16)) = make_uint4(lw[4], lw[5], lw[6], lw[7]);
}

// K=64 GEMM, 3-term bf16 split, accumulate into C[2*NBP][4]
template<int NBP>
__device__ __forceinline__ void gemm3(uint32_t aHi, uint32_t aOff,
                                      uint32_t bHi, uint32_t bLoDelta,
                                      const uint32_t* bOff, float (*C)[4])
{
    #pragma unroll
    for (int ks = 0; ks < 4; ks++){
        uint32_t Ah[4], Al[4];
        uint32_t ao = sw128(aOff + (uint32_t)ks * 32u);
        ldsm4(Ah, aHi + ao);
        ldsm4(Al, aHi + 8192u + ao);
        #pragma unroll
        for (int p = 0; p < NBP; p++){
            uint32_t Bh[4], Bl[4];
            uint32_t bo = sw128(bOff[p] + (uint32_t)ks * 32u);
            ldsm4(Bh, bHi + bo);
            ldsm4(Bl, bHi + bLoDelta + bo);
            mma16816(C[2*p],     Ah, Bh);
            mma16816(C[2*p],     Al, Bh);
            mma16816(C[2*p],     Ah, Bl);
            mma16816(C[2*p + 1], Ah, Bh + 2);
            mma16816(C[2*p + 1], Al, Bh + 2);
            mma16816(C[2*p + 1], Ah, Bl + 2);
        }
    }
}

__global__ void __launch_bounds__(THREADS, 1)
tpl_mma_kernel(const float* __restrict__ x, const float* __restrict__ y,
               const float* __restrict__ W0, const float* __restrict__ b0,
               const float* __restrict__ W1, float* __restrict__ out)
{
    extern __shared__ char sm[];
    const uint32_t smb = smem_u32(sm);
    const int tid = threadIdx.x, lane = tid & 31, w = tid >> 5;
    const int rs = w & 3;            // row strip (16 rows)
    const int h  = w >> 2;           // col half
    const int gid = lane >> 2, tig = lane & 3;

    // ---------------- stage weights (bf16 hi/lo, transposed, SW128) ----------------
    for (int idx = tid; idx < 16384; idx += THREADS){
        int c = idx >> 7, o = idx & 127;
        float v = __ldg(W0 + idx);
        uint32_t base = (c < 64) ? OFF_W0A : OFF_W0B;
        uint32_t off = sw128((uint32_t)o * 128u + (uint32_t)(c & 63) * 2u);
        __nv_bfloat16 hv = __float2bfloat16(v);
        __nv_bfloat16 lv = __float2bfloat16(v - __bfloat162float(hv));
        *(__nv_bfloat16*)(sm + base + off)          = hv;
        *(__nv_bfloat16*)(sm + base + 16384u + off) = lv;
    }
    for (int idx = tid; idx < 8192; idx += THREADS){
        int c = idx >> 6, o = idx & 63;
        float v = __ldg(W1 + idx);
        uint32_t base = (c < 64) ? OFF_W1A : OFF_W1B;
        uint32_t off = sw128((uint32_t)o * 128u + (uint32_t)(c & 63) * 2u);
        __nv_bfloat16 hv = __float2bfloat16(v);
        __nv_bfloat16 lv = __float2bfloat16(v - __bfloat162float(hv));
        *(__nv_bfloat16*)(sm + base + off)         = hv;
        *(__nv_bfloat16*)(sm + base + 8192u + off) = lv;
    }
    if (tid < 128) ((float*)(sm + OFF_B0))[tid] = __ldg(b0 + tid);

    // ---------------- per-lane ldmatrix offsets ----------------
    const uint32_t aOff = (uint32_t)(rs * 16 + (lane & 15)) * 128u
                        + (((uint32_t)lane >> 4) & 1u) * 16u;
    const uint32_t bK    = (((uint32_t)lane >> 3) & 1u) * 16u;
    const uint32_t bLnO  = (uint32_t)(lane & 7) + (((uint32_t)lane >> 4) & 1u) * 8u;
    uint32_t bOffA[4], bOffB[2];
    #pragma unroll
    for (int p = 0; p < 4; p++) bOffA[p] = ((uint32_t)(h * 64 + p * 16) + bLnO) * 128u + bK;
    #pragma unroll
    for (int p = 0; p < 2; p++) bOffB[p] = ((uint32_t)(h * 32 + p * 16) + bLnO) * 128u + bK;

    // convert mapping: strip rs's 2 warps convert strip rs's 16 rows
    const int sl = h * 32 + lane;                 // 0..63 within strip
    const int cr = rs * 16 + (sl >> 2);           // row within tile
    const int q  = sl & 3;                        // k-quarter
    float* gate2 = (float*)(sm + OFF_GATE);
    const float* b0S = (const float*)(sm + OFF_B0);
    const int barid = rs + 1;

    __syncthreads();   // weights + b0 staged

    for (int tile = blockIdx.x; tile < NTILES; tile += gridDim.x){
        const int n0 = tile * 64;

        // ---------------- convert: build X0..X3, E rows of this strip ----------------
        {
            const float* xr = x + (size_t)(n0 + cr) * 256;
            float4 yv = *(const float4*)(y + (size_t)(n0 + cr) * 4);
            uint32_t o0 = (uint32_t)cr * 128u + (uint32_t)q * 32u;
            float f[16];
            #pragma unroll
            for (int j = 0; j < 4; j++){
                float4 v = __ldg((const float4*)xr + q * 4 + j);
                f[4*j] = v.x; f[4*j+1] = v.y; f[4*j+2] = v.z; f[4*j+3] = v.w;
            }
            store16(sm, OFF_SL, o0, f);
            float b[48];
            #pragma unroll
            for (int j = 0; j < 12; j++){
                float4 v = __ldg((const float4*)xr + 16 + q * 12 + j);
                b[4*j] = v.x; b[4*j+1] = v.y; b[4*j+2] = v.z; b[4*j+3] = v.w;
            }
            float f1[16], f2[16], f3[16], fe[16];
            #pragma unroll
            for (int k = 0; k < 16; k++){
                f1[k] = b[3*k]; f2[k] = b[3*k+1]; f3[k] = b[3*k+2];
                fe[k] = IS3 * (yv.y * f1[k] + yv.z * f2[k] + yv.w * f3[k]);
            }
            store16(sm, OFF_SL + 16384u, o0, f1);
            store16(sm, OFF_SL + 32768u, o0, f2);
            store16(sm, OFF_SL + 49152u, o0, f3);
            store16(sm, OFF_SL + 65536u, o0, fe);
        }
        BARS(barid);   // strip's slices ready

        // per-fragment-row y coefficients
        const int gr0 = n0 + rs * 16 + gid, gr1 = gr0 + 8;
        const float4 y0v = *(const float4*)(y + (size_t)gr0 * 4);
        const float4 y1v = *(const float4*)(y + (size_t)gr1 * 4);

        float gown[4][4];   // h==0 warps keep gate cols 0..31 in regs

        // ---------------- phase A: S = y0*(X0@W0a) + E@W0b ----------------
        {
            float S[8][4];
            #pragma unroll
            for (int nb = 0; nb < 8; nb++){ S[nb][0]=0.f; S[nb][1]=0.f; S[nb][2]=0.f; S[nb][3]=0.f; }
            gemm3<4>(smb + OFF_SL, aOff, smb + OFF_W0A, 16384u, bOffA, S);
            #pragma unroll
            for (int nb = 0; nb < 8; nb++){
                S[nb][0] *= y0v.x; S[nb][1] *= y0v.x;
                S[nb][2] *= y1v.x; S[nb][3] *= y1v.x;
            }
            gemm3<4>(smb + OFF_SL + 65536u, aOff, smb + OFF_W0B, 16384u, bOffA, S);

            // -------- epilogue A --------
            if (h == 0){
                #pragma unroll
                for (int nb = 0; nb < 8; nb++){
                    int c0 = nb * 8 + 2 * tig;
                    float ba = b0S[c0], bb = b0S[c0 + 1];
                    float g0 = fsigmoid(S[nb][0] * ISF + ba);
                    float g1 = fsigmoid(S[nb][1] * ISF + bb);
                    float g2 = fsigmoid(S[nb][2] * ISF + ba);
                    float g3 = fsigmoid(S[nb][3] * ISF + bb);
                    if (nb < 4){
                        gown[nb][0] = g0; gown[nb][1] = g1;
                        gown[nb][2] = g2; gown[nb][3] = g3;
                    } else {
                        float2 t0 = {g0, g1}, t1 = {g2, g3};
                        *(float2*)&gate2[(rs * 16 + gid) * 34 + (nb - 4) * 8 + 2 * tig]     = t0;
                        *(float2*)&gate2[(rs * 16 + gid + 8) * 34 + (nb - 4) * 8 + 2 * tig] = t1;
                    }
                }
            } else {
                #pragma unroll
                for (int nb = 0; nb < 8; nb++){
                    int c0 = 64 + nb * 8 + 2 * tig;
                    float ba = b0S[c0], bb = b0S[c0 + 1];
                    float2 e0 = { fgelu(S[nb][0] * ISF + ba), fgelu(S[nb][1] * ISF + bb) };
                    float2 e1 = { fgelu(S[nb][2] * ISF + ba), fgelu(S[nb][3] * ISF + bb) };
                    *(float2*)(out + (size_t)gr0 * 256 + (c0 - 64)) = e0;
                    *(float2*)(out + (size_t)gr1 * 256 + (c0 - 64)) = e1;
                }
            }
        }

        // ---------------- phase B (fused ks loop, B cached across X1..X3) ----------------
        float P[4][4], Q[3][4][4];
        #pragma unroll
        for (int nb = 0; nb < 4; nb++){ P[nb][0]=0.f; P[nb][1]=0.f; P[nb][2]=0.f; P[nb][3]=0.f; }
        #pragma unroll
        for (int i = 0; i < 3; i++)
            #pragma unroll
            for (int nb = 0; nb < 4; nb++){ Q[i][nb][0]=0.f; Q[i][nb][1]=0.f; Q[i][nb][2]=0.f; Q[i][nb][3]=0.f; }

        #pragma unroll
        for (int ks = 0; ks < 4; ks++){
            const uint32_t ao = sw128(aOff + (uint32_t)ks * 32u);
            uint32_t A0h[4], A0l[4];
            ldsm4(A0h, smb + OFF_SL + ao);
            ldsm4(A0l, smb + OFF_SL + 8192u + ao);
            #pragma unroll
            for (int p = 0; p < 2; p++){
                const uint32_t bo = sw128(bOffB[p] + (uint32_t)ks * 32u);
                uint32_t Bh[4], Bl[4];
                ldsm4(Bh, smb + OFF_W1A + bo);
                ldsm4(Bl, smb + OFF_W1A + 8192u + bo);
                mma16816(P[2*p],     A0h, Bh);
                mma16816(P[2*p],     A0l, Bh);
                mma16816(P[2*p],     A0h, Bl);
                mma16816(P[2*p + 1], A0h, Bh + 2);
                mma16816(P[2*p + 1], A0l, Bh + 2);
                mma16816(P[2*p + 1], A0h, Bl + 2);
            }
            uint32_t Ah[3][4], Al[3][4];
            #pragma unroll
            for (int i = 0; i < 3; i++){
                ldsm4(Ah[i], smb + OFF_SL + 16384u * (1 + i) + ao);
                ldsm4(Al[i], smb + OFF_SL + 16384u * (1 + i) + 8192u + ao);
            }
            #pragma unroll
            for (int p = 0; p < 2; p++){
                const uint32_t bo = sw128(bOffB[p] + (uint32_t)ks * 32u);
                uint32_t Bh[4], Bl[4];
                ldsm4(Bh, smb + OFF_W1B + bo);
                ldsm4(Bl, smb + OFF_W1B + 8192u + bo);
                #pragma unroll
                for (int i = 0; i < 3; i++){
                    mma16816(Q[i][2*p],     Ah[i], Bh);
                    mma16816(Q[i][2*p],     Al[i], Bh);
                    mma16816(Q[i][2*p],     Ah[i], Bl);
                    mma16816(Q[i][2*p + 1], Ah[i], Bh + 2);
                    mma16816(Q[i][2*p + 1], Al[i], Bh + 2);
                    mma16816(Q[i][2*p + 1], Ah[i], Bl + 2);
                }
            }
        }

        BARS(barid);   // gate2 visible to h==1; strip's slice reads complete

        // ---------------- epilogue B: vec = gate * (y1i*P + y0*Q_i) ----------------
        {
            const float c0r0 = y0v.x * ISF, c0r1 = y1v.x * ISF;
            #pragma unroll
            for (int nb = 0; nb < 4; nb++){
                float2 ga, gb;
                if (h == 0){
                    ga.x = gown[nb][0]; ga.y = gown[nb][1];
                    gb.x = gown[nb][2]; gb.y = gown[nb][3];
                } else {
                    ga = *(float2*)&gate2[(rs * 16 + gid) * 34 + nb * 8 + 2 * tig];
                    gb = *(float2*)&gate2[(rs * 16 + gid + 8) * 34 + nb * 8 + 2 * tig];
                }
                float vo[3][4];
                #pragma unroll
                for (int i = 0; i < 3; i++){
                    const float c1r0 = (&y0v.x)[1 + i] * ISF, c1r1 = (&y1v.x)[1 + i] * ISF;
                    vo[i][0] = c1r0 * P[nb][0] + c0r0 * Q[i][nb][0];
                    vo[i][1] = c1r0 * P[nb][1] + c0r0 * Q[i][nb][1];
                    vo[i][2] = c1r1 * P[nb][2] + c0r1 * Q[i][nb][2];
                    vo[i][3] = c1r1 * P[nb][3] + c0r1 * Q[i][nb][3];
                }
                const int cB = h * 32 + nb * 8 + 2 * tig;
                float* o0p = out + (size_t)gr0 * 256 + 64 + 3 * cB;
                float* o1p = out + (size_t)gr1 * 256 + 64 + 3 * cB;
                float2 t;
                t.x = ga.x * vo[0][0]; t.y = ga.x * vo[1][0]; *(float2*)(o0p)     = t;
                t.x = ga.x * vo[2][0]; t.y = ga.y * vo[0][1]; *(float2*)(o0p + 2) = t;
                t.x = ga.y * vo[1][1]; t.y = ga.y * vo[2][1]; *(float2*)(o0p + 4) = t;
                t.x = gb.x * vo[0][2]; t.y = gb.x * vo[1][2]; *(float2*)(o1p)     = t;
                t.x = gb.x * vo[2][2]; t.y = gb.y * vo[0][3]; *(float2*)(o1p + 2) = t;
                t.x = gb.y * vo[1][3]; t.y = gb.y * vo[2][3]; *(float2*)(o1p + 4) = t;
            }
        }
    }
}

extern "C" void kernel_launch(void* const* d_in, const int* in_sizes, int n_in,
                              void* d_out, int out_size)
{
    (void)in_sizes; (void)n_in; (void)out_size;
    const float* x  = (const float*)d_in[0];
    const float* y  = (const float*)d_in[1];
    const float* W0 = (const float*)d_in[2];
    const float* b0 = (const float*)d_in[3];
    const float* W1 = (const float*)d_in[4];
    float* out = (float*)d_out;

    cudaFuncSetAttribute(tpl_mma_kernel,
                         cudaFuncAttributeMaxDynamicSharedMemorySize, SMEM_BYTES);

    int dev = 0;
    cudaGetDevice(&dev);
    int sms = 148;
    cudaDeviceGetAttribute(&sms, cudaDevAttrMultiProcessorCount, dev);
    int grid = sms < NTILES ? sms : NTILES;

    tpl_mma_kernel<<<grid, THREADS, SMEM_BYTES>>>(x, y, W0, b0, W1, out);
}

// round 9
// speedup vs baseline: 3.3866x; 1.0640x over previous
#include <cuda_runtime.h>
#include <cuda_bf16.h>
#include <cstdint>

#define THREADS 512
#define NTILES  2048          // 131072 / 64 rows

#define ISF   0.08838834764831845f
#define IS3   0.5773502691896258f
#define LOG2E 1.4426950408889634f

// ---------------- smem byte offsets ----------------
// slices: s=0..3 (X0,X1,X2,X3), s=4 (E); each: hi 8KB then lo 8KB
#define OFF_SL   0u
#define OFF_W0A  81920u       // W0a^T [o:128][k:64] hi 16KB, lo +16384
#define OFF_W0B  114688u
#define OFF_W1A  147456u      // W1a^T [o:64][k:64] hi 8KB, lo +8192
#define OFF_W1B  163840u
#define OFF_B0   180224u      // 128 floats
#define OFF_GATE 180736u      // 64 rows x 66 floats (all gate cols)
#define SMEM_BYTES 197632

__device__ __forceinline__ uint32_t sw128(uint32_t o){ return o ^ ((o >> 3) & 0x70); }
__device__ __forceinline__ uint32_t smem_u32(const void* p){
    uint32_t a;
    asm("{ .reg .u64 t; cvta.to.shared.u64 t, %1; cvt.u32.u64 %0, t; }" : "=r"(a) : "l"(p));
    return a;
}
__device__ __forceinline__ void ldsm4(uint32_t* r, uint32_t a){
    asm volatile("ldmatrix.sync.aligned.m8n8.x4.shared.b16 {%0,%1,%2,%3}, [%4];"
        : "=r"(r[0]), "=r"(r[1]), "=r"(r[2]), "=r"(r[3]) : "r"(a));
}
__device__ __forceinline__ void mma16816(float* c, const uint32_t* a, const uint32_t* b){
    asm volatile("mma.sync.aligned.m16n8k16.row.col.f32.bf16.bf16.f32 "
        "{%0,%1,%2,%3}, {%4,%5,%6,%7}, {%8,%9}, {%0,%1,%2,%3};"
        : "+f"(c[0]), "+f"(c[1]), "+f"(c[2]), "+f"(c[3])
        : "r"(a[0]), "r"(a[1]), "r"(a[2]), "r"(a[3]), "r"(b[0]), "r"(b[1]));
}
// per-strip barrier: 4 warps (128 threads), ids 1..4
#define BARS(id) asm volatile("bar.sync %0, %1;" :: "r"(id), "r"(128) : "memory")

__device__ __forceinline__ float ex2f(float v){ float r; asm("ex2.approx.f32 %0, %1;" : "=f"(r) : "f"(v)); return r; }
__device__ __forceinline__ float rcpf(float v){ float r; asm("rcp.approx.f32 %0, %1;" : "=f"(r) : "f"(v)); return r; }
__device__ __forceinline__ float fsigmoid(float v){ return rcpf(1.0f + ex2f(-LOG2E * v)); }
__device__ __forceinline__ float fgelu(float v){
    float u = 0.7978845608028654f * v * (1.0f + 0.044715f * v * v);
    return v - v * rcpf(1.0f + ex2f(2.8853900817779268f * u));
}
__device__ __forceinline__ uint32_t packsplit(float a, float b, uint32_t& lo){
    __nv_bfloat16 ha = __float2bfloat16(a), hb = __float2bfloat16(b);
    __nv_bfloat16 la = __float2bfloat16(a - __bfloat162float(ha));
    __nv_bfloat16 lb = __float2bfloat16(b - __bfloat162float(hb));
    lo = (uint32_t)__bfloat16_as_ushort(la) | ((uint32_t)__bfloat16_as_ushort(lb) << 16);
    return (uint32_t)__bfloat16_as_ushort(ha) | ((uint32_t)__bfloat16_as_ushort(hb) << 16);
}
// store 8 consecutive k-values (hi+lo) of one row (one 16B swizzle unit)
__device__ __forceinline__ void store8(char* sm, uint32_t base, uint32_t o0, const float* f){
    uint32_t hw[4], lw[4];
    #pragma unroll
    for (int j = 0; j < 4; j++) hw[j] = packsplit(f[2*j], f[2*j+1], lw[j]);
    *(uint4*)(sm + base + sw128(o0))         = make_uint4(hw[0], hw[1], hw[2], hw[3]);
    *(uint4*)(sm + base + 8192u + sw128(o0)) = make_uint4(lw[0], lw[1], lw[2], lw[3]);
}

// K=64 GEMM, 3-term bf16 split, accumulate into C[2*NBP][4]
template<int NBP>
__device__ __forceinline__ void gemm3(uint32_t aHi, uint32_t aOff,
                                      uint32_t bHi, uint32_t bLoDelta,
                                      const uint32_t* bOff, float (*C)[4])
{
    #pragma unroll
    for (int ks = 0; ks < 4; ks++){
        uint32_t Ah[4], Al[4];
        uint32_t ao = sw128(aOff + (uint32_t)ks * 32u);
        ldsm4(Ah, aHi + ao);
        ldsm4(Al, aHi + 8192u + ao);
        #pragma unroll
        for (int p = 0; p < NBP; p++){
            uint32_t Bh[4], Bl[4];
            uint32_t bo = sw128(bOff[p] + (uint32_t)ks * 32u);
            ldsm4(Bh, bHi + bo);
            ldsm4(Bl, bHi + bLoDelta + bo);
            mma16816(C[2*p],     Ah, Bh);
            mma16816(C[2*p],     Al, Bh);
            mma16816(C[2*p],     Ah, Bl);
            mma16816(C[2*p + 1], Ah, Bh + 2);
            mma16816(C[2*p + 1], Al, Bh + 2);
            mma16816(C[2*p + 1], Ah, Bl + 2);
        }
    }
}

__global__ void __launch_bounds__(THREADS, 1)
tpl_mma_kernel(const float* __restrict__ x, const float* __restrict__ y,
               const float* __restrict__ W0, const float* __restrict__ b0,
               const float* __restrict__ W1, float* __restrict__ out)
{
    extern __shared__ char sm[];
    const uint32_t smb = smem_u32(sm);
    const int tid = threadIdx.x, lane = tid & 31, w = tid >> 5;
    const int rs = w & 3;            // row strip (16 rows)
    const int h  = w >> 2;           // N quarter (0..3)
    const int gid = lane >> 2, tig = lane & 3;

    // ---------------- stage weights (bf16 hi/lo, transposed, SW128) ----------------
    for (int idx = tid; idx < 16384; idx += THREADS){
        int c = idx >> 7, o = idx & 127;
        float v = __ldg(W0 + idx);
        uint32_t base = (c < 64) ? OFF_W0A : OFF_W0B;
        uint32_t off = sw128((uint32_t)o * 128u + (uint32_t)(c & 63) * 2u);
        __nv_bfloat16 hv = __float2bfloat16(v);
        __nv_bfloat16 lv = __float2bfloat16(v - __bfloat162float(hv));
        *(__nv_bfloat16*)(sm + base + off)          = hv;
        *(__nv_bfloat16*)(sm + base + 16384u + off) = lv;
    }
    for (int idx = tid; idx < 8192; idx += THREADS){
        int c = idx >> 6, o = idx & 63;
        float v = __ldg(W1 + idx);
        uint32_t base = (c < 64) ? OFF_W1A : OFF_W1B;
        uint32_t off = sw128((uint32_t)o * 128u + (uint32_t)(c & 63) * 2u);
        __nv_bfloat16 hv = __float2bfloat16(v);
        __nv_bfloat16 lv = __float2bfloat16(v - __bfloat162float(hv));
        *(__nv_bfloat16*)(sm + base + off)         = hv;
        *(__nv_bfloat16*)(sm + base + 8192u + off) = lv;
    }
    if (tid < 128) ((float*)(sm + OFF_B0))[tid] = __ldg(b0 + tid);

    // ---------------- per-lane ldmatrix offsets ----------------
    const uint32_t aOff = (uint32_t)(rs * 16 + (lane & 15)) * 128u
                        + (((uint32_t)lane >> 4) & 1u) * 16u;
    const uint32_t bK    = (((uint32_t)lane >> 3) & 1u) * 16u;
    const uint32_t bLnO  = (uint32_t)(lane & 7) + (((uint32_t)lane >> 4) & 1u) * 8u;
    uint32_t bOffA[2], bOffB;
    #pragma unroll
    for (int p = 0; p < 2; p++) bOffA[p] = ((uint32_t)(h * 32 + p * 16) + bLnO) * 128u + bK;
    bOffB = ((uint32_t)(h * 16) + bLnO) * 128u + bK;

    // convert mapping: strip's 4 warps convert 16 rows, 8 threads/row, 32 cols/thread
    const int cr = rs * 16 + h * 4 + (lane >> 3);  // row within tile
    const int q  = lane & 7;                        // col-eighth
    float* gate2 = (float*)(sm + OFF_GATE);
    const float* b0S = (const float*)(sm + OFF_B0);
    const int barid = rs + 1;

    __syncthreads();   // weights + b0 staged

    for (int tile = blockIdx.x; tile < NTILES; tile += gridDim.x){
        const int n0 = tile * 64;

        // ---------------- convert: this thread handles row cr, cols [8q,8q+8) + zoneB ----------------
        {
            const float* xr = x + (size_t)(n0 + cr) * 256;
            float4 yv = *(const float4*)(y + (size_t)(n0 + cr) * 4);
            uint32_t o0 = (uint32_t)cr * 128u + (uint32_t)q * 16u;
            float f[8];
            #pragma unroll
            for (int j = 0; j < 2; j++){
                float4 v = __ldg((const float4*)xr + q * 2 + j);
                f[4*j] = v.x; f[4*j+1] = v.y; f[4*j+2] = v.z; f[4*j+3] = v.w;
            }
            store8(sm, OFF_SL, o0, f);
            float b[24];
            #pragma unroll
            for (int j = 0; j < 6; j++){
                float4 v = __ldg((const float4*)xr + 16 + q * 6 + j);
                b[4*j] = v.x; b[4*j+1] = v.y; b[4*j+2] = v.z; b[4*j+3] = v.w;
            }
            float f1[8], f2[8], f3[8], fe[8];
            #pragma unroll
            for (int k = 0; k < 8; k++){
                f1[k] = b[3*k]; f2[k] = b[3*k+1]; f3[k] = b[3*k+2];
                fe[k] = IS3 * (yv.y * f1[k] + yv.z * f2[k] + yv.w * f3[k]);
            }
            store8(sm, OFF_SL + 16384u, o0, f1);
            store8(sm, OFF_SL + 32768u, o0, f2);
            store8(sm, OFF_SL + 49152u, o0, f3);
            store8(sm, OFF_SL + 65536u, o0, fe);
        }
        BARS(barid);   // strip's slices ready

        // per-fragment-row y coefficients
        const int gr0 = n0 + rs * 16 + gid, gr1 = gr0 + 8;
        const float4 y0v = *(const float4*)(y + (size_t)gr0 * 4);
        const float4 y1v = *(const float4*)(y + (size_t)gr1 * 4);

        // ---------------- phase A: S = y0*(X0@W0a) + E@W0b  (N=32 per warp) ----------------
        {
            float S[4][4];
            #pragma unroll
            for (int nb = 0; nb < 4; nb++){ S[nb][0]=0.f; S[nb][1]=0.f; S[nb][2]=0.f; S[nb][3]=0.f; }
            gemm3<2>(smb + OFF_SL, aOff, smb + OFF_W0A, 16384u, bOffA, S);
            #pragma unroll
            for (int nb = 0; nb < 4; nb++){
                S[nb][0] *= y0v.x; S[nb][1] *= y0v.x;
                S[nb][2] *= y1v.x; S[nb][3] *= y1v.x;
            }
            gemm3<2>(smb + OFF_SL + 65536u, aOff, smb + OFF_W0B, 16384u, bOffA, S);

            // -------- epilogue A: h<2 -> gates (smem), h>=2 -> gelu (gmem) --------
            if (h < 2){
                #pragma unroll
                for (int nb = 0; nb < 4; nb++){
                    int c0 = h * 32 + nb * 8 + 2 * tig;
                    float ba = b0S[c0], bb = b0S[c0 + 1];
                    float2 t0 = { fsigmoid(S[nb][0] * ISF + ba), fsigmoid(S[nb][1] * ISF + bb) };
                    float2 t1 = { fsigmoid(S[nb][2] * ISF + ba), fsigmoid(S[nb][3] * ISF + bb) };
                    *(float2*)&gate2[(rs * 16 + gid) * 66 + c0]     = t0;
                    *(float2*)&gate2[(rs * 16 + gid + 8) * 66 + c0] = t1;
                }
            } else {
                #pragma unroll
                for (int nb = 0; nb < 4; nb++){
                    int c0 = h * 32 + nb * 8 + 2 * tig;   // 64..127
                    float ba = b0S[c0], bb = b0S[c0 + 1];
                    float2 e0 = { fgelu(S[nb][0] * ISF + ba), fgelu(S[nb][1] * ISF + bb) };
                    float2 e1 = { fgelu(S[nb][2] * ISF + ba), fgelu(S[nb][3] * ISF + bb) };
                    *(float2*)(out + (size_t)gr0 * 256 + (c0 - 64)) = e0;
                    *(float2*)(out + (size_t)gr1 * 256 + (c0 - 64)) = e1;
                }
            }
        }

        // ---------------- phase B (fused ks loop, N=16 per warp) ----------------
        float P[2][4], Q[3][2][4];
        #pragma unroll
        for (int nb = 0; nb < 2; nb++){ P[nb][0]=0.f; P[nb][1]=0.f; P[nb][2]=0.f; P[nb][3]=0.f; }
        #pragma unroll
        for (int i = 0; i < 3; i++)
            #pragma unroll
            for (int nb = 0; nb < 2; nb++){ Q[i][nb][0]=0.f; Q[i][nb][1]=0.f; Q[i][nb][2]=0.f; Q[i][nb][3]=0.f; }

        #pragma unroll
        for (int ks = 0; ks < 4; ks++){
            const uint32_t ao = sw128(aOff + (uint32_t)ks * 32u);
            const uint32_t bo = sw128(bOffB + (uint32_t)ks * 32u);
            uint32_t A0h[4], A0l[4];
            ldsm4(A0h, smb + OFF_SL + ao);
            ldsm4(A0l, smb + OFF_SL + 8192u + ao);
            {
                uint32_t Bh[4], Bl[4];
                ldsm4(Bh, smb + OFF_W1A + bo);
                ldsm4(Bl, smb + OFF_W1A + 8192u + bo);
                mma16816(P[0], A0h, Bh);
                mma16816(P[0], A0l, Bh);
                mma16816(P[0], A0h, Bl);
                mma16816(P[1], A0h, Bh + 2);
                mma16816(P[1], A0l, Bh + 2);
                mma16816(P[1], A0h, Bl + 2);
            }
            uint32_t Ah[3][4], Al[3][4];
            #pragma unroll
            for (int i = 0; i < 3; i++){
                ldsm4(Ah[i], smb + OFF_SL + 16384u * (1 + i) + ao);
                ldsm4(Al[i], smb + OFF_SL + 16384u * (1 + i) + 8192u + ao);
            }
            {
                uint32_t Bh[4], Bl[4];
                ldsm4(Bh, smb + OFF_W1B + bo);
                ldsm4(Bl, smb + OFF_W1B + 8192u + bo);
                #pragma unroll
                for (int i = 0; i < 3; i++){
                    mma16816(Q[i][0], Ah[i], Bh);
                    mma16816(Q[i][0], Al[i], Bh);
                    mma16816(Q[i][0], Ah[i], Bl);
                    mma16816(Q[i][1], Ah[i], Bh + 2);
                    mma16816(Q[i][1], Al[i], Bh + 2);
                    mma16816(Q[i][1], Ah[i], Bl + 2);
                }
            }
        }

        BARS(barid);   // gates visible; strip's slice reads complete

        // ---------------- epilogue B: vec = gate * (y1i*P + y0*Q_i) ----------------
        {
            const float c0r0 = y0v.x * ISF, c0r1 = y1v.x * ISF;
            #pragma unroll
            for (int nb = 0; nb < 2; nb++){
                const int cB = h * 16 + nb * 8 + 2 * tig;
                float2 ga = *(float2*)&gate2[(rs * 16 + gid) * 66 + cB];
                float2 gb = *(float2*)&gate2[(rs * 16 + gid + 8) * 66 + cB];
                float vo[3][4];
                #pragma unroll
                for (int i = 0; i < 3; i++){
                    const float c1r0 = (&y0v.x)[1 + i] * ISF, c1r1 = (&y1v.x)[1 + i] * ISF;
                    vo[i][0] = c1r0 * P[nb][0] + c0r0 * Q[i][nb][0];
                    vo[i][1] = c1r0 * P[nb][1] + c0r0 * Q[i][nb][1];
                    vo[i][2] = c1r1 * P[nb][2] + c0r1 * Q[i][nb][2];
                    vo[i][3] = c1r1 * P[nb][3] + c0r1 * Q[i][nb][3];
                }
                float* o0p = out + (size_t)gr0 * 256 + 64 + 3 * cB;
                float* o1p = out + (size_t)gr1 * 256 + 64 + 3 * cB;
                float2 t;
                t.x = ga.x * vo[0][0]; t.y = ga.x * vo[1][0]; *(float2*)(o0p)     = t;
                t.x = ga.x * vo[2][0]; t.y = ga.y * vo[0][1]; *(float2*)(o0p + 2) = t;
                t.x = ga.y * vo[1][1]; t.y = ga.y * vo[2][1]; *(float2*)(o0p + 4) = t;
                t.x = gb.x * vo[0][2]; t.y = gb.x * vo[1][2]; *(float2*)(o1p)     = t;
                t.x = gb.x * vo[2][2]; t.y = gb.y * vo[0][3]; *(float2*)(o1p + 2) = t;
                t.x = gb.y * vo[1][3]; t.y = gb.y * vo[2][3]; *(float2*)(o1p + 4) = t;
            }
        }
    }
}

extern "C" void kernel_launch(void* const* d_in, const int* in_sizes, int n_in,
                              void* d_out, int out_size)
{
    (void)in_sizes; (void)n_in; (void)out_size;
    const float* x  = (const float*)d_in[0];
    const float* y  = (const float*)d_in[1];
    const float* W0 = (const float*)d_in[2];
    const float* b0 = (const float*)d_in[3];
    const float* W1 = (const float*)d_in[4];
    float* out = (float*)d_out;

    cudaFuncSetAttribute(tpl_mma_kernel,
                         cudaFuncAttributeMaxDynamicSharedMemorySize, SMEM_BYTES);

    int dev = 0;
    cudaGetDevice(&dev);
    int sms = 148;
    cudaDeviceGetAttribute(&sms, cudaDevAttrMultiProcessorCount, dev);
    int grid = sms < NTILES ? sms : NTILES;

    tpl_mma_kernel<<<grid, THREADS, SMEM_BYTES>>>(x, y, W0, b0, W1, out);
}